// round 2
// baseline (speedup 1.0000x reference)
#include <cuda_runtime.h>
#include <math.h>

#define HIDDEN 768
#define NHEADS 12
#define HD 64
#define WIN 14
#define TOK 196                 // WIN*WIN
#define BATCH 256
#define MTOK (BATCH * TOK)      // 50176
#define NQKV (3 * HIDDEN)       // 2304

// Scratch (allocation-free rule: __device__ globals)
__device__ float g_qkv[(size_t)MTOK * NQKV];    // 50176 x 2304
__device__ float g_att[(size_t)MTOK * HIDDEN];  // 50176 x 768

// ---------------------------------------------------------------------------
// SGEMM with packed f32x2 FMAs:  C[M,N] = A[M,K] @ W[N,K]^T + bias[N]
// BM=BN=128, BK=8, 256 threads, 8x8 per thread (as 8x4 f32x2 pairs).
// A is stored duplicated pairwise in smem so a-operands are (a,a) packs.
// Requires M%128==0, N%128==0, K%8==0 (true for all three uses).
// ---------------------------------------------------------------------------
#define BM 128
#define BN 128
#define BKS 8

__global__ __launch_bounds__(256, 2)
void sgemm_bias_f32x2(const float* __restrict__ A, const float* __restrict__ W,
                      const float* __restrict__ bias, float* __restrict__ C,
                      int N, int K) {
    __shared__ __align__(16) float As[BKS][2 * BM];  // duplicated A
    __shared__ __align__(16) float Bs[BKS][BN];

    const int bm = blockIdx.y * BM;
    const int bn = blockIdx.x * BN;
    const int tid = threadIdx.x;
    const int tx = tid & 15;        // 0..15  (N direction)
    const int ty = tid >> 4;        // 0..15  (M direction)
    const int lrow = tid >> 1;      // 0..127 loader row
    const int lcol = (tid & 1) * 4; // 0 or 4 loader k-offset

    const float* Ap = A + (size_t)(bm + lrow) * K + lcol;
    const float* Wp = W + (size_t)(bn + lrow) * K + lcol;

    unsigned long long acc[8][4];
#pragma unroll
    for (int i = 0; i < 8; i++)
#pragma unroll
        for (int j = 0; j < 4; j++) acc[i][j] = 0ull;

    float4 av = *(const float4*)Ap;
    float4 wv = *(const float4*)Wp;

    for (int k0 = 0; k0 < K; k0 += BKS) {
        *(float2*)&As[lcol + 0][2 * lrow] = make_float2(av.x, av.x);
        *(float2*)&As[lcol + 1][2 * lrow] = make_float2(av.y, av.y);
        *(float2*)&As[lcol + 2][2 * lrow] = make_float2(av.z, av.z);
        *(float2*)&As[lcol + 3][2 * lrow] = make_float2(av.w, av.w);
        Bs[lcol + 0][lrow] = wv.x;
        Bs[lcol + 1][lrow] = wv.y;
        Bs[lcol + 2][lrow] = wv.z;
        Bs[lcol + 3][lrow] = wv.w;
        __syncthreads();
        if (k0 + BKS < K) {  // prefetch next tile while computing
            av = *(const float4*)(Ap + k0 + BKS);
            wv = *(const float4*)(Wp + k0 + BKS);
        }
#pragma unroll
        for (int kk = 0; kk < BKS; kk++) {
            unsigned long long a2[8], b2[4];
#pragma unroll
            for (int i = 0; i < 8; i++)
                a2[i] = *(const unsigned long long*)&As[kk][(ty * 8 + i) * 2];
#pragma unroll
            for (int j = 0; j < 4; j++)
                b2[j] = *(const unsigned long long*)&Bs[kk][tx * 8 + 2 * j];
#pragma unroll
            for (int i = 0; i < 8; i++)
#pragma unroll
                for (int j = 0; j < 4; j++)
                    asm("fma.rn.f32x2 %0, %1, %2, %0;"
                        : "+l"(acc[i][j]) : "l"(a2[i]), "l"(b2[j]));
        }
        __syncthreads();
    }

#pragma unroll
    for (int i = 0; i < 8; i++) {
        const int row = bm + ty * 8 + i;
        float* Crow = C + (size_t)row * N + bn + tx * 8;
#pragma unroll
        for (int j = 0; j < 4; j++) {
            float2 u = *(float2*)&acc[i][j];
            Crow[2 * j + 0] = u.x + bias[bn + tx * 8 + 2 * j + 0];
            Crow[2 * j + 1] = u.y + bias[bn + tx * 8 + 2 * j + 1];
        }
    }
}

// ---------------------------------------------------------------------------
// Attention: one block per (batch*head). 256 threads = 8 warps.
// Each warp processes 4 queries per pass, 7 passes cover 196 queries.
// K kept d-major in smem (conflict-free QK^T), V row-major (conflict-free PV).
// Rel-pos bias computed per query from padded smem tables.
// ---------------------------------------------------------------------------
#define KT_OFF   0                       // 64*196
#define VS_OFF   (KT_OFF + 64 * TOK)     // 196*64
#define RH_OFF   (VS_OFF + TOK * 64)     // 27*68 (padded rows)
#define RW_OFF   (RH_OFF + 27 * 68)
#define QR_OFF   (RW_OFF + 27 * 68)      // 32 queries * 64
#define RLH_OFF  (QR_OFF + 32 * 64)      // 32 * 16 (pad 14->16)
#define RLW_OFF  (RLH_OFF + 32 * 16)
#define PSM_OFF  (RLW_OFF + 32 * 16)     // 32 * 196
#define ATT_SMEM_FLOATS (PSM_OFF + 32 * TOK)
#define ATT_SMEM_BYTES  (ATT_SMEM_FLOATS * 4)

__global__ __launch_bounds__(256, 1)
void attn_kernel(const float* __restrict__ qkv,
                 const float* __restrict__ rel_pos_h,
                 const float* __restrict__ rel_pos_w,
                 float* __restrict__ att_out) {
    extern __shared__ __align__(16) float sm[];
    float* Kt   = sm + KT_OFF;
    float* Vs   = sm + VS_OFF;
    float* Rh   = sm + RH_OFF;
    float* Rw   = sm + RW_OFF;
    float* Qrow = sm + QR_OFF;
    float* RelH = sm + RLH_OFF;
    float* RelW = sm + RLW_OFF;
    float* Psm  = sm + PSM_OFF;

    const int bh = blockIdx.x;
    const int b = bh / NHEADS;
    const int head = bh % NHEADS;
    const int tid = threadIdx.x;
    const int warp = tid >> 5;
    const int lane = tid & 31;

    const float* base = qkv + (size_t)b * TOK * NQKV + head * HD;

    // Load K (transposed, d-major) and V (row-major)
    for (int i = tid; i < TOK * HD; i += 256) {
        const int t = i >> 6, d = i & 63;
        Kt[d * TOK + t] = base[(size_t)t * NQKV + HIDDEN + d];
        Vs[i]           = base[(size_t)t * NQKV + 2 * HIDDEN + d];
    }
    // Rel-pos tables, padded row stride 68 (kills bank conflicts)
    for (int i = tid; i < 27 * 64; i += 256) {
        const int r = i >> 6, c = i & 63;
        Rh[r * 68 + c] = rel_pos_h[i];
        Rw[r * 68 + c] = rel_pos_w[i];
    }
    __syncthreads();

    const float scale = 0.125f;  // 64^-0.5

    for (int pass = 0; pass < 7; pass++) {
        const int q0 = pass * 32 + warp * 4;

        // Load 4 query rows into this warp's smem slot (raw, unscaled)
#pragma unroll
        for (int qq = 0; qq < 4; qq++) {
            const int qt = q0 + qq;
            if (qt < TOK) {
                Qrow[(warp * 4 + qq) * 64 + lane]      = base[(size_t)qt * NQKV + lane];
                Qrow[(warp * 4 + qq) * 64 + lane + 32] = base[(size_t)qt * NQKV + lane + 32];
            }
        }
        __syncwarp();

        // Rel-pos bias: lanes 0..13 -> rel_h rows, lanes 14..27 -> rel_w rows
#pragma unroll
        for (int qq = 0; qq < 4; qq++) {
            const int qt = q0 + qq;
            if (qt < TOK && lane < 28) {
                const int qh = qt / WIN, qw = qt % WIN;
                const float* R;
                int rr;
                if (lane < 14) { rr = qh - lane + 13;        R = Rh; }
                else           { rr = qw - (lane - 14) + 13; R = Rw; }
                const float* qp = &Qrow[(warp * 4 + qq) * 64];
                float acc = 0.f;
#pragma unroll 16
                for (int c = 0; c < 64; c++) acc += qp[c] * R[rr * 68 + c];
                if (lane < 14) RelH[(warp * 4 + qq) * 16 + lane]      = acc;
                else           RelW[(warp * 4 + qq) * 16 + lane - 14] = acc;
            }
        }
        __syncwarp();

        // QK^T: lane owns keys lane, lane+32, ..., lane+192 (7 slots)
        float dot[4][7];
#pragma unroll
        for (int qq = 0; qq < 4; qq++)
#pragma unroll
            for (int j = 0; j < 7; j++) dot[qq][j] = 0.f;

        int kcl[7];
#pragma unroll
        for (int j = 0; j < 7; j++) {
            int k = lane + 32 * j;
            kcl[j] = k < TOK ? k : (TOK - 1);
        }
#pragma unroll 8
        for (int c = 0; c < 64; c++) {
            float kv[7];
#pragma unroll
            for (int j = 0; j < 7; j++) kv[j] = Kt[c * TOK + kcl[j]];
#pragma unroll
            for (int qq = 0; qq < 4; qq++) {
                const float qv = Qrow[(warp * 4 + qq) * 64 + c];
#pragma unroll
                for (int j = 0; j < 7; j++) dot[qq][j] += qv * kv[j];
            }
        }

        // Softmax per query (warp-wide over 196 keys)
        float inv[4];
#pragma unroll
        for (int qq = 0; qq < 4; qq++) {
            float s[7];
            float m = -1e30f;
#pragma unroll
            for (int j = 0; j < 7; j++) {
                const int k = lane + 32 * j;
                if (k < TOK) {
                    s[j] = scale * dot[qq][j]
                         + RelH[(warp * 4 + qq) * 16 + k / WIN]
                         + RelW[(warp * 4 + qq) * 16 + k % WIN];
                } else s[j] = -1e30f;
                m = fmaxf(m, s[j]);
            }
#pragma unroll
            for (int off = 16; off > 0; off >>= 1)
                m = fmaxf(m, __shfl_xor_sync(0xffffffffu, m, off));
            float p[7], sum = 0.f;
#pragma unroll
            for (int j = 0; j < 7; j++) {
                const int k = lane + 32 * j;
                p[j] = (k < TOK) ? __expf(s[j] - m) : 0.f;
                sum += p[j];
            }
#pragma unroll
            for (int off = 16; off > 0; off >>= 1)
                sum += __shfl_xor_sync(0xffffffffu, sum, off);
            inv[qq] = 1.f / sum;
#pragma unroll
            for (int j = 0; j < 7; j++) {
                const int k = lane + 32 * j;
                if (k < TOK) Psm[(warp * 4 + qq) * TOK + k] = p[j];
            }
        }
        __syncwarp();

        // PV: lane owns output dims lane and lane+32
        float acc[4][2];
#pragma unroll
        for (int qq = 0; qq < 4; qq++) { acc[qq][0] = 0.f; acc[qq][1] = 0.f; }
#pragma unroll 4
        for (int k = 0; k < TOK; k++) {
            const float v1 = Vs[k * 64 + lane];
            const float v2 = Vs[k * 64 + lane + 32];
#pragma unroll
            for (int qq = 0; qq < 4; qq++) {
                const float p = Psm[(warp * 4 + qq) * TOK + k];
                acc[qq][0] += p * v1;
                acc[qq][1] += p * v2;
            }
        }

        // Store: layout (b*196+t, head*64+d) so proj GEMM reads row-major
#pragma unroll
        for (int qq = 0; qq < 4; qq++) {
            const int qt = q0 + qq;
            if (qt < TOK) {
                float* o = att_out + (size_t)(b * TOK + qt) * HIDDEN + head * HD;
                o[lane]      = acc[qq][0] * inv[qq];
                o[lane + 32] = acc[qq][1] * inv[qq];
            }
        }
        __syncwarp();  // protect Qrow/Psm before next pass overwrites
    }
}

// ---------------------------------------------------------------------------
extern "C" void kernel_launch(void* const* d_in, const int* in_sizes, int n_in,
                              void* d_out, int out_size) {
    const float* hidden = (const float*)d_in[0];   // (256,14,14,768)
    const float* qkv_w  = (const float*)d_in[1];   // (2304,768)
    const float* qkv_b  = (const float*)d_in[2];   // (2304,)
    const float* proj_w = (const float*)d_in[3];   // (768,768)
    const float* proj_b = (const float*)d_in[4];   // (768,)
    const float* rel_h  = (const float*)d_in[5];   // (27,64)
    const float* rel_w  = (const float*)d_in[6];   // (27,64)
    float* out = (float*)d_out;                    // (256,14,14,768)

    void* p_qkv = nullptr;
    void* p_att = nullptr;
    cudaGetSymbolAddress(&p_qkv, g_qkv);
    cudaGetSymbolAddress(&p_att, g_att);

    cudaFuncSetAttribute(attn_kernel,
                         cudaFuncAttributeMaxDynamicSharedMemorySize,
                         ATT_SMEM_BYTES);

    // 1) QKV projection: (50176,768) @ (768,2304)^T + b
    sgemm_bias_f32x2<<<dim3(NQKV / BN, MTOK / BM), 256>>>(
        hidden, qkv_w, qkv_b, (float*)p_qkv, NQKV, HIDDEN);

    // 2) Attention with decomposed rel-pos bias
    attn_kernel<<<BATCH * NHEADS, 256, ATT_SMEM_BYTES>>>(
        (const float*)p_qkv, rel_h, rel_w, (float*)p_att);

    // 3) Output projection: (50176,768) @ (768,768)^T + b
    sgemm_bias_f32x2<<<dim3(HIDDEN / BN, MTOK / BM), 256>>>(
        (const float*)p_att, proj_w, proj_b, out, HIDDEN, HIDDEN);
}

// round 3
// speedup vs baseline: 2.3395x; 2.3395x over previous
#include <cuda_runtime.h>
#include <math.h>
#include <stdint.h>

#define HIDDEN 768
#define NHEADS 12
#define HD 64
#define WIN 14
#define TOK 196                 // WIN*WIN
#define BATCH 256
#define MTOK (BATCH * TOK)      // 50176
#define NQKV (3 * HIDDEN)       // 2304

// Scratch (allocation-free rule: __device__ globals)
__device__ float g_qkv[(size_t)MTOK * NQKV];    // 50176 x 2304
__device__ float g_att[(size_t)MTOK * HIDDEN];  // 50176 x 768

// ---------------------------------------------------------------------------
// TF32 tensor-core GEMM:  C[M,N] = A[M,K] @ W[N,K]^T + bias[N]
// mma.sync.aligned.m16n8k8.row.col.f32.tf32.tf32.f32
// BM=BN=128, BK=16, 256 threads (8 warps), warp tile 64x32 (4x4 mma atoms).
// fp32 -> tf32 conversion (cvt.rna) applied when staging tiles into smem.
// Requires M%128==0, N%128==0, K%16==0.
// ---------------------------------------------------------------------------
#define BKT 16
#define SSTR (BKT + 4)   // padded smem row stride (conflict-free fragment loads)

__device__ __forceinline__ uint32_t f2tf32(float x) {
    uint32_t u;
    asm("cvt.rna.tf32.f32 %0, %1;" : "=r"(u) : "f"(x));
    return u;
}

__device__ __forceinline__ void mma_tf32(float c[4], const uint32_t a[4],
                                         const uint32_t b[2]) {
    asm("mma.sync.aligned.m16n8k8.row.col.f32.tf32.tf32.f32 "
        "{%0,%1,%2,%3}, {%4,%5,%6,%7}, {%8,%9}, {%0,%1,%2,%3};"
        : "+f"(c[0]), "+f"(c[1]), "+f"(c[2]), "+f"(c[3])
        : "r"(a[0]), "r"(a[1]), "r"(a[2]), "r"(a[3]), "r"(b[0]), "r"(b[1]));
}

__global__ __launch_bounds__(256, 2)
void gemm_tf32(const float* __restrict__ A, const float* __restrict__ W,
               const float* __restrict__ bias, float* __restrict__ C,
               int N, int K) {
    __shared__ uint32_t As[128][SSTR];
    __shared__ uint32_t Bs[128][SSTR];

    const int bm = blockIdx.y * 128;
    const int bn = blockIdx.x * 128;
    const int tid = threadIdx.x;
    const int warp = tid >> 5;
    const int lane = tid & 31;
    const int g = lane >> 2;        // group id 0..7
    const int tg = lane & 3;        // thread-in-group 0..3
    const int wm = (warp >> 2) * 64;  // warp m-offset (0 or 64)
    const int wn = (warp & 3) * 32;   // warp n-offset (0,32,64,96)

    // Loader mapping: idx in 0..511 -> row = idx>>2, col4 = (idx&3)*4
    const int r0 = tid >> 2;                 // rows 0..63
    const int c0 = (tid & 3) * 4;
    const int r1 = r0 + 64;                  // rows 64..127

    float acc[4][4][4];
#pragma unroll
    for (int im = 0; im < 4; im++)
#pragma unroll
        for (int in = 0; in < 4; in++)
#pragma unroll
            for (int q = 0; q < 4; q++) acc[im][in][q] = 0.f;

    const float* Ap0 = A + (size_t)(bm + r0) * K + c0;
    const float* Ap1 = A + (size_t)(bm + r1) * K + c0;
    const float* Wp0 = W + (size_t)(bn + r0) * K + c0;
    const float* Wp1 = W + (size_t)(bn + r1) * K + c0;

    float4 av0 = *(const float4*)Ap0;
    float4 av1 = *(const float4*)Ap1;
    float4 wv0 = *(const float4*)Wp0;
    float4 wv1 = *(const float4*)Wp1;

    for (int k0 = 0; k0 < K; k0 += BKT) {
        // Stage tiles into smem, converting to tf32 bits
        As[r0][c0 + 0] = f2tf32(av0.x); As[r0][c0 + 1] = f2tf32(av0.y);
        As[r0][c0 + 2] = f2tf32(av0.z); As[r0][c0 + 3] = f2tf32(av0.w);
        As[r1][c0 + 0] = f2tf32(av1.x); As[r1][c0 + 1] = f2tf32(av1.y);
        As[r1][c0 + 2] = f2tf32(av1.z); As[r1][c0 + 3] = f2tf32(av1.w);
        Bs[r0][c0 + 0] = f2tf32(wv0.x); Bs[r0][c0 + 1] = f2tf32(wv0.y);
        Bs[r0][c0 + 2] = f2tf32(wv0.z); Bs[r0][c0 + 3] = f2tf32(wv0.w);
        Bs[r1][c0 + 0] = f2tf32(wv1.x); Bs[r1][c0 + 1] = f2tf32(wv1.y);
        Bs[r1][c0 + 2] = f2tf32(wv1.z); Bs[r1][c0 + 3] = f2tf32(wv1.w);
        __syncthreads();

        if (k0 + BKT < K) {  // prefetch next tiles
            av0 = *(const float4*)(Ap0 + k0 + BKT);
            av1 = *(const float4*)(Ap1 + k0 + BKT);
            wv0 = *(const float4*)(Wp0 + k0 + BKT);
            wv1 = *(const float4*)(Wp1 + k0 + BKT);
        }

#pragma unroll
        for (int ks = 0; ks < 2; ks++) {
            const int kb = ks * 8;
            uint32_t af[4][4], bf[4][2];
#pragma unroll
            for (int im = 0; im < 4; im++) {
                const int r = wm + im * 16 + g;
                af[im][0] = As[r][kb + tg];
                af[im][1] = As[r + 8][kb + tg];
                af[im][2] = As[r][kb + tg + 4];
                af[im][3] = As[r + 8][kb + tg + 4];
            }
#pragma unroll
            for (int in = 0; in < 4; in++) {
                const int nr = wn + in * 8 + g;
                bf[in][0] = Bs[nr][kb + tg];
                bf[in][1] = Bs[nr][kb + tg + 4];
            }
#pragma unroll
            for (int im = 0; im < 4; im++)
#pragma unroll
                for (int in = 0; in < 4; in++)
                    mma_tf32(acc[im][in], af[im], bf[in]);
        }
        __syncthreads();
    }

    // Epilogue: add bias, write fp32
#pragma unroll
    for (int im = 0; im < 4; im++) {
        const int row = bm + wm + im * 16 + g;
#pragma unroll
        for (int in = 0; in < 4; in++) {
            const int col = bn + wn + in * 8 + 2 * tg;
            const float b0 = bias[col], b1 = bias[col + 1];
            float* Cr = C + (size_t)row * N + col;
            Cr[0] = acc[im][in][0] + b0;
            Cr[1] = acc[im][in][1] + b1;
            float* Cr8 = C + (size_t)(row + 8) * N + col;
            Cr8[0] = acc[im][in][2] + b0;
            Cr8[1] = acc[im][in][3] + b1;
        }
    }
}

// ---------------------------------------------------------------------------
// Attention: one block per (batch*head). 256 threads = 8 warps.
// Each warp processes 4 queries per pass, 7 passes cover 196 queries.
// ---------------------------------------------------------------------------
#define KT_OFF   0                       // 64*196
#define VS_OFF   (KT_OFF + 64 * TOK)     // 196*64
#define RH_OFF   (VS_OFF + TOK * 64)     // 27*68 (padded rows)
#define RW_OFF   (RH_OFF + 27 * 68)
#define QR_OFF   (RW_OFF + 27 * 68)      // 32 queries * 64
#define RLH_OFF  (QR_OFF + 32 * 64)      // 32 * 16 (pad 14->16)
#define RLW_OFF  (RLH_OFF + 32 * 16)
#define PSM_OFF  (RLW_OFF + 32 * 16)     // 32 * 196
#define ATT_SMEM_FLOATS (PSM_OFF + 32 * TOK)
#define ATT_SMEM_BYTES  (ATT_SMEM_FLOATS * 4)

__global__ __launch_bounds__(256, 1)
void attn_kernel(const float* __restrict__ qkv,
                 const float* __restrict__ rel_pos_h,
                 const float* __restrict__ rel_pos_w,
                 float* __restrict__ att_out) {
    extern __shared__ __align__(16) float sm[];
    float* Kt   = sm + KT_OFF;
    float* Vs   = sm + VS_OFF;
    float* Rh   = sm + RH_OFF;
    float* Rw   = sm + RW_OFF;
    float* Qrow = sm + QR_OFF;
    float* RelH = sm + RLH_OFF;
    float* RelW = sm + RLW_OFF;
    float* Psm  = sm + PSM_OFF;

    const int bh = blockIdx.x;
    const int b = bh / NHEADS;
    const int head = bh % NHEADS;
    const int tid = threadIdx.x;
    const int warp = tid >> 5;
    const int lane = tid & 31;

    const float* base = qkv + (size_t)b * TOK * NQKV + head * HD;

    for (int i = tid; i < TOK * HD; i += 256) {
        const int t = i >> 6, d = i & 63;
        Kt[d * TOK + t] = base[(size_t)t * NQKV + HIDDEN + d];
        Vs[i]           = base[(size_t)t * NQKV + 2 * HIDDEN + d];
    }
    for (int i = tid; i < 27 * 64; i += 256) {
        const int r = i >> 6, c = i & 63;
        Rh[r * 68 + c] = rel_pos_h[i];
        Rw[r * 68 + c] = rel_pos_w[i];
    }
    __syncthreads();

    const float scale = 0.125f;  // 64^-0.5

    for (int pass = 0; pass < 7; pass++) {
        const int q0 = pass * 32 + warp * 4;

#pragma unroll
        for (int qq = 0; qq < 4; qq++) {
            const int qt = q0 + qq;
            if (qt < TOK) {
                Qrow[(warp * 4 + qq) * 64 + lane]      = base[(size_t)qt * NQKV + lane];
                Qrow[(warp * 4 + qq) * 64 + lane + 32] = base[(size_t)qt * NQKV + lane + 32];
            }
        }
        __syncwarp();

#pragma unroll
        for (int qq = 0; qq < 4; qq++) {
            const int qt = q0 + qq;
            if (qt < TOK && lane < 28) {
                const int qh = qt / WIN, qw = qt % WIN;
                const float* R;
                int rr;
                if (lane < 14) { rr = qh - lane + 13;        R = Rh; }
                else           { rr = qw - (lane - 14) + 13; R = Rw; }
                const float* qp = &Qrow[(warp * 4 + qq) * 64];
                float acc = 0.f;
#pragma unroll 16
                for (int c = 0; c < 64; c++) acc += qp[c] * R[rr * 68 + c];
                if (lane < 14) RelH[(warp * 4 + qq) * 16 + lane]      = acc;
                else           RelW[(warp * 4 + qq) * 16 + lane - 14] = acc;
            }
        }
        __syncwarp();

        float dot[4][7];
#pragma unroll
        for (int qq = 0; qq < 4; qq++)
#pragma unroll
            for (int j = 0; j < 7; j++) dot[qq][j] = 0.f;

        int kcl[7];
#pragma unroll
        for (int j = 0; j < 7; j++) {
            int k = lane + 32 * j;
            kcl[j] = k < TOK ? k : (TOK - 1);
        }
#pragma unroll 8
        for (int c = 0; c < 64; c++) {
            float kv[7];
#pragma unroll
            for (int j = 0; j < 7; j++) kv[j] = Kt[c * TOK + kcl[j]];
#pragma unroll
            for (int qq = 0; qq < 4; qq++) {
                const float qv = Qrow[(warp * 4 + qq) * 64 + c];
#pragma unroll
                for (int j = 0; j < 7; j++) dot[qq][j] += qv * kv[j];
            }
        }

        float inv[4];
#pragma unroll
        for (int qq = 0; qq < 4; qq++) {
            float s[7];
            float m = -1e30f;
#pragma unroll
            for (int j = 0; j < 7; j++) {
                const int k = lane + 32 * j;
                if (k < TOK) {
                    s[j] = scale * dot[qq][j]
                         + RelH[(warp * 4 + qq) * 16 + k / WIN]
                         + RelW[(warp * 4 + qq) * 16 + k % WIN];
                } else s[j] = -1e30f;
                m = fmaxf(m, s[j]);
            }
#pragma unroll
            for (int off = 16; off > 0; off >>= 1)
                m = fmaxf(m, __shfl_xor_sync(0xffffffffu, m, off));
            float p[7], sum = 0.f;
#pragma unroll
            for (int j = 0; j < 7; j++) {
                const int k = lane + 32 * j;
                p[j] = (k < TOK) ? __expf(s[j] - m) : 0.f;
                sum += p[j];
            }
#pragma unroll
            for (int off = 16; off > 0; off >>= 1)
                sum += __shfl_xor_sync(0xffffffffu, sum, off);
            inv[qq] = 1.f / sum;
#pragma unroll
            for (int j = 0; j < 7; j++) {
                const int k = lane + 32 * j;
                if (k < TOK) Psm[(warp * 4 + qq) * TOK + k] = p[j];
            }
        }
        __syncwarp();

        float acc[4][2];
#pragma unroll
        for (int qq = 0; qq < 4; qq++) { acc[qq][0] = 0.f; acc[qq][1] = 0.f; }
#pragma unroll 4
        for (int k = 0; k < TOK; k++) {
            const float v1 = Vs[k * 64 + lane];
            const float v2 = Vs[k * 64 + lane + 32];
#pragma unroll
            for (int qq = 0; qq < 4; qq++) {
                const float p = Psm[(warp * 4 + qq) * TOK + k];
                acc[qq][0] += p * v1;
                acc[qq][1] += p * v2;
            }
        }

#pragma unroll
        for (int qq = 0; qq < 4; qq++) {
            const int qt = q0 + qq;
            if (qt < TOK) {
                float* o = att_out + (size_t)(b * TOK + qt) * HIDDEN + head * HD;
                o[lane]      = acc[qq][0] * inv[qq];
                o[lane + 32] = acc[qq][1] * inv[qq];
            }
        }
        __syncwarp();
    }
}

// ---------------------------------------------------------------------------
extern "C" void kernel_launch(void* const* d_in, const int* in_sizes, int n_in,
                              void* d_out, int out_size) {
    const float* hidden = (const float*)d_in[0];   // (256,14,14,768)
    const float* qkv_w  = (const float*)d_in[1];   // (2304,768)
    const float* qkv_b  = (const float*)d_in[2];   // (2304,)
    const float* proj_w = (const float*)d_in[3];   // (768,768)
    const float* proj_b = (const float*)d_in[4];   // (768,)
    const float* rel_h  = (const float*)d_in[5];   // (27,64)
    const float* rel_w  = (const float*)d_in[6];   // (27,64)
    float* out = (float*)d_out;                    // (256,14,14,768)

    void* p_qkv = nullptr;
    void* p_att = nullptr;
    cudaGetSymbolAddress(&p_qkv, g_qkv);
    cudaGetSymbolAddress(&p_att, g_att);

    cudaFuncSetAttribute(attn_kernel,
                         cudaFuncAttributeMaxDynamicSharedMemorySize,
                         ATT_SMEM_BYTES);

    // 1) QKV projection: (50176,768) @ (768,2304)^T + b   [tf32 tensor cores]
    gemm_tf32<<<dim3(NQKV / 128, MTOK / 128), 256>>>(
        hidden, qkv_w, qkv_b, (float*)p_qkv, NQKV, HIDDEN);

    // 2) Attention with decomposed rel-pos bias
    attn_kernel<<<BATCH * NHEADS, 256, ATT_SMEM_BYTES>>>(
        (const float*)p_qkv, rel_h, rel_w, (float*)p_att);

    // 3) Output projection: (50176,768) @ (768,768)^T + b [tf32 tensor cores]
    gemm_tf32<<<dim3(HIDDEN / 128, MTOK / 128), 256>>>(
        (const float*)p_att, proj_w, proj_b, out, HIDDEN, HIDDEN);
}

// round 4
// speedup vs baseline: 2.7828x; 1.1895x over previous
#include <cuda_runtime.h>
#include <math.h>
#include <stdint.h>

#define HIDDEN 768
#define NHEADS 12
#define HD 64
#define WIN 14
#define TOK 196                 // WIN*WIN
#define BATCH 256
#define MTOK (BATCH * TOK)      // 50176
#define NQKV (3 * HIDDEN)       // 2304

// Scratch (allocation-free rule: __device__ globals)
__device__ float g_qkv[(size_t)MTOK * NQKV];    // 50176 x 2304
__device__ float g_att[(size_t)MTOK * HIDDEN];  // 50176 x 768

__device__ __forceinline__ uint32_t f2tf32(float x) {
    uint32_t u;
    asm("cvt.rna.tf32.f32 %0, %1;" : "=r"(u) : "f"(x));
    return u;
}

__device__ __forceinline__ void mma_tf32(float c[4], const uint32_t a[4],
                                         const uint32_t b[2]) {
    asm("mma.sync.aligned.m16n8k8.row.col.f32.tf32.tf32.f32 "
        "{%0,%1,%2,%3}, {%4,%5,%6,%7}, {%8,%9}, {%0,%1,%2,%3};"
        : "+f"(c[0]), "+f"(c[1]), "+f"(c[2]), "+f"(c[3])
        : "r"(a[0]), "r"(a[1]), "r"(a[2]), "r"(a[3]), "r"(b[0]), "r"(b[1]));
}

// ---------------------------------------------------------------------------
// TF32 tensor-core GEMM:  C[M,N] = A[M,K] @ W[N,K]^T + bias[N]
// BM=BN=128, BK=16, 256 threads (8 warps), warp tile 64x32 (4x4 mma atoms).
// ---------------------------------------------------------------------------
#define BKT 16
#define SSTR (BKT + 4)

__global__ __launch_bounds__(256, 2)
void gemm_tf32(const float* __restrict__ A, const float* __restrict__ W,
               const float* __restrict__ bias, float* __restrict__ C,
               int N, int K) {
    __shared__ uint32_t As[128][SSTR];
    __shared__ uint32_t Bs[128][SSTR];

    const int bm = blockIdx.y * 128;
    const int bn = blockIdx.x * 128;
    const int tid = threadIdx.x;
    const int warp = tid >> 5;
    const int lane = tid & 31;
    const int g = lane >> 2;
    const int tg = lane & 3;
    const int wm = (warp >> 2) * 64;
    const int wn = (warp & 3) * 32;

    const int r0 = tid >> 2;
    const int c0 = (tid & 3) * 4;
    const int r1 = r0 + 64;

    float acc[4][4][4];
#pragma unroll
    for (int im = 0; im < 4; im++)
#pragma unroll
        for (int in = 0; in < 4; in++)
#pragma unroll
            for (int q = 0; q < 4; q++) acc[im][in][q] = 0.f;

    const float* Ap0 = A + (size_t)(bm + r0) * K + c0;
    const float* Ap1 = A + (size_t)(bm + r1) * K + c0;
    const float* Wp0 = W + (size_t)(bn + r0) * K + c0;
    const float* Wp1 = W + (size_t)(bn + r1) * K + c0;

    float4 av0 = *(const float4*)Ap0;
    float4 av1 = *(const float4*)Ap1;
    float4 wv0 = *(const float4*)Wp0;
    float4 wv1 = *(const float4*)Wp1;

    for (int k0 = 0; k0 < K; k0 += BKT) {
        As[r0][c0 + 0] = f2tf32(av0.x); As[r0][c0 + 1] = f2tf32(av0.y);
        As[r0][c0 + 2] = f2tf32(av0.z); As[r0][c0 + 3] = f2tf32(av0.w);
        As[r1][c0 + 0] = f2tf32(av1.x); As[r1][c0 + 1] = f2tf32(av1.y);
        As[r1][c0 + 2] = f2tf32(av1.z); As[r1][c0 + 3] = f2tf32(av1.w);
        Bs[r0][c0 + 0] = f2tf32(wv0.x); Bs[r0][c0 + 1] = f2tf32(wv0.y);
        Bs[r0][c0 + 2] = f2tf32(wv0.z); Bs[r0][c0 + 3] = f2tf32(wv0.w);
        Bs[r1][c0 + 0] = f2tf32(wv1.x); Bs[r1][c0 + 1] = f2tf32(wv1.y);
        Bs[r1][c0 + 2] = f2tf32(wv1.z); Bs[r1][c0 + 3] = f2tf32(wv1.w);
        __syncthreads();

        if (k0 + BKT < K) {
            av0 = *(const float4*)(Ap0 + k0 + BKT);
            av1 = *(const float4*)(Ap1 + k0 + BKT);
            wv0 = *(const float4*)(Wp0 + k0 + BKT);
            wv1 = *(const float4*)(Wp1 + k0 + BKT);
        }

#pragma unroll
        for (int ks = 0; ks < 2; ks++) {
            const int kb = ks * 8;
            uint32_t af[4][4], bf[4][2];
#pragma unroll
            for (int im = 0; im < 4; im++) {
                const int r = wm + im * 16 + g;
                af[im][0] = As[r][kb + tg];
                af[im][1] = As[r + 8][kb + tg];
                af[im][2] = As[r][kb + tg + 4];
                af[im][3] = As[r + 8][kb + tg + 4];
            }
#pragma unroll
            for (int in = 0; in < 4; in++) {
                const int nr = wn + in * 8 + g;
                bf[in][0] = Bs[nr][kb + tg];
                bf[in][1] = Bs[nr][kb + tg + 4];
            }
#pragma unroll
            for (int im = 0; im < 4; im++)
#pragma unroll
                for (int in = 0; in < 4; in++)
                    mma_tf32(acc[im][in], af[im], bf[in]);
        }
        __syncthreads();
    }

#pragma unroll
    for (int im = 0; im < 4; im++) {
        const int row = bm + wm + im * 16 + g;
#pragma unroll
        for (int in = 0; in < 4; in++) {
            const int col = bn + wn + in * 8 + 2 * tg;
            const float b0 = bias[col], b1 = bias[col + 1];
            float* Cr = C + (size_t)row * N + col;
            Cr[0] = acc[im][in][0] + b0;
            Cr[1] = acc[im][in][1] + b1;
            float* Cr8 = C + (size_t)(row + 8) * N + col;
            Cr8[0] = acc[im][in][2] + b0;
            Cr8[1] = acc[im][in][3] + b1;
        }
    }
}

// ---------------------------------------------------------------------------
// Tensor-core attention: one block per (batch*head), 256 threads = 8 warps.
// Keys padded 196->208 (26 n-tiles of 8). Queries processed in 4 passes of 64
// (4 m-tiles of 16). QK^T and PV via m16n8k8 tf32 MMA. Softmax + decomposed
// rel-pos bias in SIMT. Smem strides chosen so stride mod 32 == 4-spacing
// (68, 212) => conflict-free fragment loads.
// ---------------------------------------------------------------------------
#define KP 208
#define QT 64
#define QS 68    // Qp/Ks stride (k-dim major): 68 mod 32 = 4 -> 4g spacing
#define VS2 212  // Vt/Ssm stride (key major): 212 mod 32 = 20 -> spacing 4

#define KS_OFF  0                           // 208*68
#define QP_OFF  (KS_OFF + KP * QS)          // 64*68
#define VT_OFF  (QP_OFF + QT * QS)          // 64*212
#define SS_OFF  (VT_OFF + 64 * VS2)         // 64*212
#define RH_OFF  (SS_OFF + 64 * VS2)         // 27*68
#define RW_OFF  (RH_OFF + 27 * 68)
#define RLH_OFF (RW_OFF + 27 * 68)          // 64*16
#define RLW_OFF (RLH_OFF + 64 * 16)
#define SIV_OFF (RLW_OFF + 64 * 16)         // 64
#define ATT_SMEM_FLOATS (SIV_OFF + 64)
#define ATT_SMEM_BYTES  (ATT_SMEM_FLOATS * 4)

__global__ __launch_bounds__(256, 1)
void attn_mma(const float* __restrict__ qkv,
              const float* __restrict__ rel_pos_h,
              const float* __restrict__ rel_pos_w,
              float* __restrict__ att_out) {
    extern __shared__ __align__(16) float sm[];
    float*    Ks   = sm + KS_OFF;
    float*    Qp   = sm + QP_OFF;
    float*    Vt   = sm + VT_OFF;
    float*    Ssm  = sm + SS_OFF;
    float*    Rh   = sm + RH_OFF;
    float*    Rw   = sm + RW_OFF;
    float*    RelH = sm + RLH_OFF;
    float*    RelW = sm + RLW_OFF;
    float*    Sinv = sm + SIV_OFF;
    uint32_t* Ksu  = (uint32_t*)Ks;
    uint32_t* Qpu  = (uint32_t*)Qp;
    uint32_t* Vtu  = (uint32_t*)Vt;
    uint32_t* Ssu  = (uint32_t*)Ssm;

    const int bh = blockIdx.x;
    const int b = bh / NHEADS;
    const int head = bh % NHEADS;
    const int tid = threadIdx.x;
    const int warp = tid >> 5;
    const int lane = tid & 31;
    const int g = lane >> 2;
    const int tg = lane & 3;
    const int mt = warp >> 1;     // m-tile 0..3
    const int half = warp & 1;    // key/dim half

    const float* base = qkv + (size_t)b * TOK * NQKV + head * HD;

    // Stage K (row-major, zero-padded) and V^T as tf32
    for (int i = tid; i < KP * 64; i += 256) {
        const int t = i >> 6, d = i & 63;
        float kv = 0.f, vv = 0.f;
        if (t < TOK) {
            kv = base[(size_t)t * NQKV + HIDDEN + d];
            vv = base[(size_t)t * NQKV + 2 * HIDDEN + d];
        }
        Ksu[t * QS + d] = f2tf32(kv);
        Vtu[d * VS2 + t] = f2tf32(vv);
    }
    for (int i = tid; i < 27 * 64; i += 256) {
        const int r = i >> 6, c = i & 63;
        Rh[r * 68 + c] = rel_pos_h[i];
        Rw[r * 68 + c] = rel_pos_w[i];
    }
    __syncthreads();

    const float scale = 0.125f;  // 64^-0.5

    for (int pass = 0; pass < 4; pass++) {
        const int q0 = pass * QT;

        // Stage 64 query rows (tf32; reusable as fp32 for rel-bias)
        for (int i = tid; i < QT * 64; i += 256) {
            const int q = i >> 6, d = i & 63;
            const int qt = q0 + q;
            const float v = (qt < TOK) ? base[(size_t)qt * NQKV + d] : 0.f;
            Qpu[q * QS + d] = f2tf32(v);
        }
        __syncthreads();

        // Rel-pos bias: 64 q x 28 dots, float2-vectorized (7 per thread)
#pragma unroll
        for (int it = 0; it < 7; it++) {
            const int i = tid + 256 * it;
            const int q = i / 28, c = i % 28;
            const int qt = q0 + q;
            if (qt < TOK) {
                const int qh = qt / WIN, qw = qt % WIN;
                const float* R;
                int rr;
                if (c < 14) { rr = qh - c + 13;        R = Rh; }
                else        { rr = qw - (c - 14) + 13; R = Rw; }
                const float2* qp2 = (const float2*)(Qp + q * QS);
                const float2* r2  = (const float2*)(R + rr * 68);
                float acc = 0.f;
#pragma unroll
                for (int u = 0; u < 32; u++) {
                    const float2 a = qp2[u], bb = r2[u];
                    acc += a.x * bb.x + a.y * bb.y;
                }
                if (c < 14) RelH[q * 16 + c]      = acc;
                else        RelW[q * 16 + c - 14] = acc;
            }
        }

        // QK^T: warp = (m-tile, key-half); 13 n-tiles of 8 keys per warp
        float s[13][4];
#pragma unroll
        for (int j = 0; j < 13; j++)
#pragma unroll
            for (int q = 0; q < 4; q++) s[j][q] = 0.f;

#pragma unroll
        for (int ks = 0; ks < 8; ks++) {
            const int kb = ks * 8;
            uint32_t af[4];
            const int r = mt * 16 + g;
            af[0] = Qpu[r * QS + kb + tg];
            af[1] = Qpu[(r + 8) * QS + kb + tg];
            af[2] = Qpu[r * QS + kb + tg + 4];
            af[3] = Qpu[(r + 8) * QS + kb + tg + 4];
#pragma unroll
            for (int j = 0; j < 13; j++) {
                const int kn = (half * 13 + j) * 8;
                uint32_t bf[2];
                bf[0] = Ksu[(kn + g) * QS + kb + tg];
                bf[1] = Ksu[(kn + g) * QS + kb + tg + 4];
                mma_tf32(s[j], af, bf);
            }
        }
        // Store raw scores
#pragma unroll
        for (int j = 0; j < 13; j++) {
            const int kn = (half * 13 + j) * 8;
            const int r = mt * 16 + g;
            Ssm[r * VS2 + kn + 2 * tg]           = s[j][0];
            Ssm[r * VS2 + kn + 2 * tg + 1]       = s[j][1];
            Ssm[(r + 8) * VS2 + kn + 2 * tg]     = s[j][2];
            Ssm[(r + 8) * VS2 + kn + 2 * tg + 1] = s[j][3];
        }
        __syncthreads();

        // Softmax: warp per row, 8 rows per warp
#pragma unroll
        for (int rr8 = 0; rr8 < 8; rr8++) {
            const int r = warp + rr8 * 8;
            const int qt = q0 + r;
            if (qt < TOK) {
                float sv[7];
                float m = -1e30f;
#pragma unroll
                for (int j = 0; j < 7; j++) {
                    const int k = lane + 32 * j;
                    if (k < TOK) {
                        sv[j] = Ssm[r * VS2 + k] * scale
                              + RelH[r * 16 + k / WIN]
                              + RelW[r * 16 + k % WIN];
                    } else sv[j] = -1e30f;
                    m = fmaxf(m, sv[j]);
                }
#pragma unroll
                for (int off = 16; off > 0; off >>= 1)
                    m = fmaxf(m, __shfl_xor_sync(0xffffffffu, m, off));
                float p[7], sum = 0.f;
#pragma unroll
                for (int j = 0; j < 7; j++) {
                    const int k = lane + 32 * j;
                    p[j] = (k < TOK) ? __expf(sv[j] - m) : 0.f;
                    sum += p[j];
                }
#pragma unroll
                for (int off = 16; off > 0; off >>= 1)
                    sum += __shfl_xor_sync(0xffffffffu, sum, off);
                if (lane == 0) Sinv[r] = 1.f / sum;
#pragma unroll
                for (int j = 0; j < 7; j++) {
                    const int k = lane + 32 * j;
                    if (k < KP) Ssm[r * VS2 + k] = p[j];
                }
            }
        }
        __syncthreads();

        // PV: warp = (m-tile, d-half); 4 n-tiles of 8 dims per warp
        float o[4][4];
#pragma unroll
        for (int jn = 0; jn < 4; jn++)
#pragma unroll
            for (int q = 0; q < 4; q++) o[jn][q] = 0.f;

#pragma unroll
        for (int ks = 0; ks < 26; ks++) {
            const int kb = ks * 8;
            uint32_t af[4];
            const int r = mt * 16 + g;
            af[0] = Ssu[r * VS2 + kb + tg];
            af[1] = Ssu[(r + 8) * VS2 + kb + tg];
            af[2] = Ssu[r * VS2 + kb + tg + 4];
            af[3] = Ssu[(r + 8) * VS2 + kb + tg + 4];
#pragma unroll
            for (int jn = 0; jn < 4; jn++) {
                const int nd = half * 32 + jn * 8 + g;
                uint32_t bf[2];
                bf[0] = Vtu[nd * VS2 + kb + tg];
                bf[1] = Vtu[nd * VS2 + kb + tg + 4];
                mma_tf32(o[jn], af, bf);
            }
        }

        // Epilogue: normalize by 1/sum, scatter to (token, head*64+d)
        {
            const int qt0 = q0 + mt * 16 + g;
            const int qt1 = qt0 + 8;
            const float inv0 = (qt0 < TOK) ? Sinv[mt * 16 + g] : 0.f;
            const float inv1 = (qt1 < TOK) ? Sinv[mt * 16 + g + 8] : 0.f;
#pragma unroll
            for (int jn = 0; jn < 4; jn++) {
                const int d = half * 32 + jn * 8 + 2 * tg;
                if (qt0 < TOK) {
                    float* o0 = att_out + (size_t)(b * TOK + qt0) * HIDDEN + head * HD + d;
                    o0[0] = o[jn][0] * inv0;
                    o0[1] = o[jn][1] * inv0;
                }
                if (qt1 < TOK) {
                    float* o1 = att_out + (size_t)(b * TOK + qt1) * HIDDEN + head * HD + d;
                    o1[0] = o[jn][2] * inv1;
                    o1[1] = o[jn][3] * inv1;
                }
            }
        }
        __syncthreads();
    }
}

// ---------------------------------------------------------------------------
extern "C" void kernel_launch(void* const* d_in, const int* in_sizes, int n_in,
                              void* d_out, int out_size) {
    const float* hidden = (const float*)d_in[0];
    const float* qkv_w  = (const float*)d_in[1];
    const float* qkv_b  = (const float*)d_in[2];
    const float* proj_w = (const float*)d_in[3];
    const float* proj_b = (const float*)d_in[4];
    const float* rel_h  = (const float*)d_in[5];
    const float* rel_w  = (const float*)d_in[6];
    float* out = (float*)d_out;

    void* p_qkv = nullptr;
    void* p_att = nullptr;
    cudaGetSymbolAddress(&p_qkv, g_qkv);
    cudaGetSymbolAddress(&p_att, g_att);

    cudaFuncSetAttribute(attn_mma,
                         cudaFuncAttributeMaxDynamicSharedMemorySize,
                         ATT_SMEM_BYTES);

    // 1) QKV projection (tf32 tensor cores)
    gemm_tf32<<<dim3(NQKV / 128, MTOK / 128), 256>>>(
        hidden, qkv_w, qkv_b, (float*)p_qkv, NQKV, HIDDEN);

    // 2) Attention (tf32 tensor cores + SIMT softmax/rel-bias)
    attn_mma<<<BATCH * NHEADS, 256, ATT_SMEM_BYTES>>>(
        (const float*)p_qkv, rel_h, rel_w, (float*)p_att);

    // 3) Output projection (tf32 tensor cores)
    gemm_tf32<<<dim3(HIDDEN / 128, MTOK / 128), 256>>>(
        (const float*)p_att, proj_w, proj_b, out, HIDDEN, HIDDEN);
}

// round 6
// speedup vs baseline: 2.8421x; 1.0213x over previous
#include <cuda_runtime.h>
#include <math.h>
#include <stdint.h>

#define HIDDEN 768
#define NHEADS 12
#define HD 64
#define WIN 14
#define TOK 196                 // WIN*WIN
#define BATCH 256
#define MTOK (BATCH * TOK)      // 50176
#define NQKV (3 * HIDDEN)       // 2304

// Scratch (allocation-free rule: __device__ globals)
__device__ float g_qkv[(size_t)MTOK * NQKV];    // 50176 x 2304
__device__ float g_att[(size_t)MTOK * HIDDEN];  // 50176 x 768

__device__ __forceinline__ uint32_t f2tf32(float x) {
    uint32_t u;
    asm("cvt.rna.tf32.f32 %0, %1;" : "=r"(u) : "f"(x));
    return u;
}

__device__ __forceinline__ uint4 cvt4(float4 v) {
    return make_uint4(f2tf32(v.x), f2tf32(v.y), f2tf32(v.z), f2tf32(v.w));
}

__device__ __forceinline__ void mma_tf32(float c[4], const uint32_t a[4],
                                         const uint32_t b[2]) {
    asm("mma.sync.aligned.m16n8k8.row.col.f32.tf32.tf32.f32 "
        "{%0,%1,%2,%3}, {%4,%5,%6,%7}, {%8,%9}, {%0,%1,%2,%3};"
        : "+f"(c[0]), "+f"(c[1]), "+f"(c[2]), "+f"(c[3])
        : "r"(a[0]), "r"(a[1]), "r"(a[2]), "r"(a[3]), "r"(b[0]), "r"(b[1]));
}

// ---------------------------------------------------------------------------
// TF32 tensor-core GEMM:  C[M,N] = A[M,K] @ W[N,K]^T + bias[N]
// BM=BN=128, BK=16, 256 threads (8 warps), warp tile 64x32.
// Double-buffered smem: one __syncthreads per k-tile; LDG(t+1) issued before
// MMA(t); staging via STS.128.
// ---------------------------------------------------------------------------
#define BKT 16
#define SSTR (BKT + 4)

__global__ __launch_bounds__(256, 2)
void gemm_tf32(const float* __restrict__ A, const float* __restrict__ W,
               const float* __restrict__ bias, float* __restrict__ C,
               int N, int K) {
    __shared__ uint32_t As[2][128][SSTR];
    __shared__ uint32_t Bs[2][128][SSTR];

    const int bm = blockIdx.y * 128;
    const int bn = blockIdx.x * 128;
    const int tid = threadIdx.x;
    const int warp = tid >> 5;
    const int lane = tid & 31;
    const int g = lane >> 2;
    const int tg = lane & 3;
    const int wm = (warp >> 2) * 64;
    const int wn = (warp & 3) * 32;

    const int r0 = tid >> 2;
    const int c0 = (tid & 3) * 4;
    const int r1 = r0 + 64;

    float acc[4][4][4];
#pragma unroll
    for (int im = 0; im < 4; im++)
#pragma unroll
        for (int in = 0; in < 4; in++)
#pragma unroll
            for (int q = 0; q < 4; q++) acc[im][in][q] = 0.f;

    const float* Ap0 = A + (size_t)(bm + r0) * K + c0;
    const float* Ap1 = A + (size_t)(bm + r1) * K + c0;
    const float* Wp0 = W + (size_t)(bn + r0) * K + c0;
    const float* Wp1 = W + (size_t)(bn + r1) * K + c0;

    float4 av0 = *(const float4*)Ap0;
    float4 av1 = *(const float4*)Ap1;
    float4 wv0 = *(const float4*)Wp0;
    float4 wv1 = *(const float4*)Wp1;

    // Prologue: stage tile 0 into buffer 0
    *(uint4*)&As[0][r0][c0] = cvt4(av0);
    *(uint4*)&As[0][r1][c0] = cvt4(av1);
    *(uint4*)&Bs[0][r0][c0] = cvt4(wv0);
    *(uint4*)&Bs[0][r1][c0] = cvt4(wv1);
    __syncthreads();

    int p = 0;
    for (int k0 = 0; k0 < K; k0 += BKT, p ^= 1) {
        const bool more = (k0 + BKT) < K;
        if (more) {  // issue next-tile loads before MMA: latency hidden
            av0 = *(const float4*)(Ap0 + k0 + BKT);
            av1 = *(const float4*)(Ap1 + k0 + BKT);
            wv0 = *(const float4*)(Wp0 + k0 + BKT);
            wv1 = *(const float4*)(Wp1 + k0 + BKT);
        }

#pragma unroll
        for (int ks = 0; ks < 2; ks++) {
            const int kb = ks * 8;
            uint32_t af[4][4], bf[4][2];
#pragma unroll
            for (int im = 0; im < 4; im++) {
                const int r = wm + im * 16 + g;
                af[im][0] = As[p][r][kb + tg];
                af[im][1] = As[p][r + 8][kb + tg];
                af[im][2] = As[p][r][kb + tg + 4];
                af[im][3] = As[p][r + 8][kb + tg + 4];
            }
#pragma unroll
            for (int in = 0; in < 4; in++) {
                const int nr = wn + in * 8 + g;
                bf[in][0] = Bs[p][nr][kb + tg];
                bf[in][1] = Bs[p][nr][kb + tg + 4];
            }
#pragma unroll
            for (int im = 0; im < 4; im++)
#pragma unroll
                for (int in = 0; in < 4; in++)
                    mma_tf32(acc[im][in], af[im], bf[in]);
        }

        if (more) {  // stage next tile into the other buffer
            *(uint4*)&As[p ^ 1][r0][c0] = cvt4(av0);
            *(uint4*)&As[p ^ 1][r1][c0] = cvt4(av1);
            *(uint4*)&Bs[p ^ 1][r0][c0] = cvt4(wv0);
            *(uint4*)&Bs[p ^ 1][r1][c0] = cvt4(wv1);
        }
        __syncthreads();
    }

#pragma unroll
    for (int im = 0; im < 4; im++) {
        const int row = bm + wm + im * 16 + g;
#pragma unroll
        for (int in = 0; in < 4; in++) {
            const int col = bn + wn + in * 8 + 2 * tg;
            const float b0 = bias[col], b1 = bias[col + 1];
            float* Cr = C + (size_t)row * N + col;
            Cr[0] = acc[im][in][0] + b0;
            Cr[1] = acc[im][in][1] + b1;
            float* Cr8 = C + (size_t)(row + 8) * N + col;
            Cr8[0] = acc[im][in][2] + b0;
            Cr8[1] = acc[im][in][3] + b1;
        }
    }
}

// ---------------------------------------------------------------------------
// Tensor-core attention: one block per (batch*head), 512 threads = 16 warps.
// Keys padded 196->224 (28 n-tiles of 8). Queries in 4 passes of 64.
// warp = (mt = warp>>2, quar = warp&3):
//   QK^T : warp covers m-tile mt x 7 key-tiles [quar*7, quar*7+7)
//   PV   : warp covers m-tile mt x 16 dims [quar*16, quar*16+16)
//   softmax: 4 rows per warp.
// Strides 68 / 228 (== 4 mod 32) => conflict-free MMA fragment loads.
// V staged via a 64x65 smem transpose (reuses Q buffer) so both the gmem
// read and all smem phases are conflict-free.
// ---------------------------------------------------------------------------
#define KP 224
#define QT 64
#define QS 68
#define VS2 228

#define KS_OFF  0                           // 224*68  = 15232
#define QP_OFF  (KS_OFF + KP * QS)          // 64*68   = 4352 (also 64x65 tmp)
#define VT_OFF  (QP_OFF + QT * QS)          // 64*228  = 14592
#define SS_OFF  (VT_OFF + 64 * VS2)         // 64*228  = 14592
#define RH_OFF  (SS_OFF + 64 * VS2)         // 27*68
#define RW_OFF  (RH_OFF + 27 * 68)
#define RLH_OFF (RW_OFF + 27 * 68)          // 64*16
#define RLW_OFF (RLH_OFF + 64 * 16)
#define SIV_OFF (RLW_OFF + 64 * 16)         // 64
#define ATT_SMEM_FLOATS (SIV_OFF + 64)
#define ATT_SMEM_BYTES  (ATT_SMEM_FLOATS * 4)

__global__ __launch_bounds__(512, 1)
void attn_mma(const float* __restrict__ qkv,
              const float* __restrict__ rel_pos_h,
              const float* __restrict__ rel_pos_w,
              float* __restrict__ att_out) {
    extern __shared__ __align__(16) float sm[];
    float*    Ks   = sm + KS_OFF;
    float*    Qp   = sm + QP_OFF;
    float*    Vt   = sm + VT_OFF;
    float*    Ssm  = sm + SS_OFF;
    float*    Rh   = sm + RH_OFF;
    float*    Rw   = sm + RW_OFF;
    float*    RelH = sm + RLH_OFF;
    float*    RelW = sm + RLW_OFF;
    float*    Sinv = sm + SIV_OFF;
    uint32_t* Ksu  = (uint32_t*)Ks;
    uint32_t* Qpu  = (uint32_t*)Qp;
    uint32_t* Vtu  = (uint32_t*)Vt;
    uint32_t* Ssu  = (uint32_t*)Ssm;

    const int bh = blockIdx.x;
    const int b = bh / NHEADS;
    const int head = bh % NHEADS;
    const int tid = threadIdx.x;
    const int warp = tid >> 5;
    const int lane = tid & 31;
    const int g = lane >> 2;
    const int tg = lane & 3;
    const int mt = warp >> 2;     // m-tile 0..3
    const int quar = warp & 3;    // quarter 0..3

    const float* base = qkv + (size_t)b * TOK * NQKV + head * HD;

    // Stage K (row-major tf32, zero-padded), rel-pos tables
    for (int i = tid; i < KP * 64; i += 512) {
        const int t = i >> 6, d = i & 63;
        const float kv = (t < TOK) ? base[(size_t)t * NQKV + HIDDEN + d] : 0.f;
        Ksu[t * QS + d] = f2tf32(kv);
    }
    for (int i = tid; i < 27 * 64; i += 512) {
        const int r = i >> 6, c = i & 63;
        Rh[r * 68 + c] = rel_pos_h[i];
        Rw[r * 68 + c] = rel_pos_w[i];
    }

    // Stage V^T via 64x65 transpose chunks through Qp (conflict-free)
    {
        float* Tmp = Qp;  // 64 x 65 <= 64 x 68
        for (int c = 0; c < 4; c++) {
            const int t0 = c * 56;
            for (int i = tid; i < 56 * 64; i += 512) {
                const int tt = i >> 6, d = i & 63;
                const int t = t0 + tt;
                Tmp[tt * 65 + d] =
                    (t < TOK) ? base[(size_t)t * NQKV + 2 * HIDDEN + d] : 0.f;
            }
            __syncthreads();
            for (int i = tid; i < 56 * 64; i += 512) {
                const int d = i / 56, tt = i % 56;
                Vtu[d * VS2 + t0 + tt] = f2tf32(Tmp[tt * 65 + d]);
            }
            __syncthreads();
        }
    }

    const float scale = 0.125f;  // 64^-0.5

    for (int pass = 0; pass < 4; pass++) {
        const int q0 = pass * QT;

        // Stage 64 query rows (tf32 bits; also readable as fp32 for bias)
        for (int i = tid; i < QT * 64; i += 512) {
            const int q = i >> 6, d = i & 63;
            const int qt = q0 + q;
            const float v = (qt < TOK) ? base[(size_t)qt * NQKV + d] : 0.f;
            Qpu[q * QS + d] = f2tf32(v);
        }
        __syncthreads();

        // Rel-pos bias: 64 q x 28 dots, float2-vectorized
#pragma unroll
        for (int it = 0; it < 4; it++) {
            const int i = tid + 512 * it;
            if (i < 64 * 28) {
                const int q = i / 28, c = i % 28;
                const int qt = q0 + q;
                if (qt < TOK) {
                    const int qh = qt / WIN, qw = qt % WIN;
                    const float* R;
                    int rr;
                    if (c < 14) { rr = qh - c + 13;        R = Rh; }
                    else        { rr = qw - (c - 14) + 13; R = Rw; }
                    const float2* qp2 = (const float2*)(Qp + q * QS);
                    const float2* r2  = (const float2*)(R + rr * 68);
                    float acc = 0.f;
#pragma unroll
                    for (int u = 0; u < 32; u++) {
                        const float2 a = qp2[u], bb = r2[u];
                        acc += a.x * bb.x + a.y * bb.y;
                    }
                    if (c < 14) RelH[q * 16 + c]      = acc;
                    else        RelW[q * 16 + c - 14] = acc;
                }
            }
        }

        // QK^T: 7 key-tiles per warp
        float s[7][4];
#pragma unroll
        for (int j = 0; j < 7; j++)
#pragma unroll
            for (int q = 0; q < 4; q++) s[j][q] = 0.f;

#pragma unroll
        for (int ks = 0; ks < 8; ks++) {
            const int kb = ks * 8;
            uint32_t af[4];
            const int r = mt * 16 + g;
            af[0] = Qpu[r * QS + kb + tg];
            af[1] = Qpu[(r + 8) * QS + kb + tg];
            af[2] = Qpu[r * QS + kb + tg + 4];
            af[3] = Qpu[(r + 8) * QS + kb + tg + 4];
#pragma unroll
            for (int j = 0; j < 7; j++) {
                const int kn = (quar * 7 + j) * 8;
                uint32_t bf[2];
                bf[0] = Ksu[(kn + g) * QS + kb + tg];
                bf[1] = Ksu[(kn + g) * QS + kb + tg + 4];
                mma_tf32(s[j], af, bf);
            }
        }
#pragma unroll
        for (int j = 0; j < 7; j++) {
            const int kn = (quar * 7 + j) * 8;
            const int r = mt * 16 + g;
            *(float2*)&Ssm[r * VS2 + kn + 2 * tg] =
                make_float2(s[j][0], s[j][1]);
            *(float2*)&Ssm[(r + 8) * VS2 + kn + 2 * tg] =
                make_float2(s[j][2], s[j][3]);
        }
        __syncthreads();

        // Softmax: 4 rows per warp
#pragma unroll
        for (int rr8 = 0; rr8 < 4; rr8++) {
            const int r = warp + rr8 * 16;
            const int qt = q0 + r;
            if (qt < TOK) {
                float sv[7];
                float m = -1e30f;
#pragma unroll
                for (int j = 0; j < 7; j++) {
                    const int k = lane + 32 * j;
                    if (k < TOK) {
                        sv[j] = Ssm[r * VS2 + k] * scale
                              + RelH[r * 16 + k / WIN]
                              + RelW[r * 16 + k % WIN];
                    } else sv[j] = -1e30f;
                    m = fmaxf(m, sv[j]);
                }
#pragma unroll
                for (int off = 16; off > 0; off >>= 1)
                    m = fmaxf(m, __shfl_xor_sync(0xffffffffu, m, off));
                float p[7], sum = 0.f;
#pragma unroll
                for (int j = 0; j < 7; j++) {
                    const int k = lane + 32 * j;
                    p[j] = (k < TOK) ? __expf(sv[j] - m) : 0.f;
                    sum += p[j];
                }
#pragma unroll
                for (int off = 16; off > 0; off >>= 1)
                    sum += __shfl_xor_sync(0xffffffffu, sum, off);
                if (lane == 0) Sinv[r] = 1.f / sum;
#pragma unroll
                for (int j = 0; j < 7; j++)
                    Ssm[r * VS2 + lane + 32 * j] = p[j];
            }
        }
        __syncthreads();

        // PV: 2 dim-tiles per warp over 28 k-tiles
        float o[2][4];
#pragma unroll
        for (int jn = 0; jn < 2; jn++)
#pragma unroll
            for (int q = 0; q < 4; q++) o[jn][q] = 0.f;

#pragma unroll
        for (int ks = 0; ks < 28; ks++) {
            const int kb = ks * 8;
            uint32_t af[4];
            const int r = mt * 16 + g;
            af[0] = Ssu[r * VS2 + kb + tg];
            af[1] = Ssu[(r + 8) * VS2 + kb + tg];
            af[2] = Ssu[r * VS2 + kb + tg + 4];
            af[3] = Ssu[(r + 8) * VS2 + kb + tg + 4];
#pragma unroll
            for (int jn = 0; jn < 2; jn++) {
                const int nd = quar * 16 + jn * 8 + g;
                uint32_t bf[2];
                bf[0] = Vtu[nd * VS2 + kb + tg];
                bf[1] = Vtu[nd * VS2 + kb + tg + 4];
                mma_tf32(o[jn], af, bf);
            }
        }

        // Epilogue
        {
            const int qt0 = q0 + mt * 16 + g;
            const int qt1 = qt0 + 8;
            const float inv0 = (qt0 < TOK) ? Sinv[mt * 16 + g] : 0.f;
            const float inv1 = (qt1 < TOK) ? Sinv[mt * 16 + g + 8] : 0.f;
#pragma unroll
            for (int jn = 0; jn < 2; jn++) {
                const int d = quar * 16 + jn * 8 + 2 * tg;
                if (qt0 < TOK) {
                    float* o0 = att_out + (size_t)(b * TOK + qt0) * HIDDEN
                              + head * HD + d;
                    *(float2*)o0 = make_float2(o[jn][0] * inv0, o[jn][1] * inv0);
                }
                if (qt1 < TOK) {
                    float* o1 = att_out + (size_t)(b * TOK + qt1) * HIDDEN
                              + head * HD + d;
                    *(float2*)o1 = make_float2(o[jn][2] * inv1, o[jn][3] * inv1);
                }
            }
        }
        __syncthreads();
    }
}

// ---------------------------------------------------------------------------
extern "C" void kernel_launch(void* const* d_in, const int* in_sizes, int n_in,
                              void* d_out, int out_size) {
    const float* hidden = (const float*)d_in[0];
    const float* qkv_w  = (const float*)d_in[1];
    const float* qkv_b  = (const float*)d_in[2];
    const float* proj_w = (const float*)d_in[3];
    const float* proj_b = (const float*)d_in[4];
    const float* rel_h  = (const float*)d_in[5];
    const float* rel_w  = (const float*)d_in[6];
    float* out = (float*)d_out;

    void* p_qkv = nullptr;
    void* p_att = nullptr;
    cudaGetSymbolAddress(&p_qkv, g_qkv);
    cudaGetSymbolAddress(&p_att, g_att);

    cudaFuncSetAttribute(attn_mma,
                         cudaFuncAttributeMaxDynamicSharedMemorySize,
                         ATT_SMEM_BYTES);

    // 1) QKV projection (tf32 tensor cores, double-buffered)
    gemm_tf32<<<dim3(NQKV / 128, MTOK / 128), 256>>>(
        hidden, qkv_w, qkv_b, (float*)p_qkv, NQKV, HIDDEN);

    // 2) Attention (tf32 tensor cores, 16 warps/block)
    attn_mma<<<BATCH * NHEADS, 512, ATT_SMEM_BYTES>>>(
        (const float*)p_qkv, rel_h, rel_w, (float*)p_att);

    // 3) Output projection (tf32 tensor cores, double-buffered)
    gemm_tf32<<<dim3(HIDDEN / 128, MTOK / 128), 256>>>(
        (const float*)p_att, proj_w, proj_b, out, HIDDEN, HIDDEN);
}